// round 3
// baseline (speedup 1.0000x reference)
#include <cuda_runtime.h>
#include <cuda_bf16.h>
#include <math.h>

// Problem shape (fixed): B=64, T=1024, I=256, H=1024, P=10
// Output depends only on batch sample 63 (h[-1]); LSTM recurrence is
// independent per batch row, so we compute only sample 63's trajectory.

#define T_STEPS 1024
#define IDIM    256
#define HDIM    1024
#define PDIM    10

#define REC_CTAS    128   // each owns 8 h-units -> 32 gate columns
#define REC_THREADS 512   // 16 warps; warp w owns rows [64w, 64w+64)
#define NBUF        4     // h rotation depth (skew tolerance 3)

// Scratch (static device globals; no allocation allowed)
__device__ float    g_xproj[T_STEPS * 4 * HDIM];  // [t][gate][h], bias folded
__device__ float    g_hbuf[NBUF][HDIM];           // rotating hidden state
__device__ unsigned g_bar;

// ---------------------------------------------------------------------------
// Memory-model helpers
// ---------------------------------------------------------------------------
__device__ __forceinline__ unsigned ld_acquire_gpu(const unsigned* p) {
    unsigned v;
    asm volatile("ld.acquire.gpu.u32 %0, [%1];" : "=r"(v) : "l"(p) : "memory");
    return v;
}
__device__ __forceinline__ void red_release_gpu(unsigned* p, unsigned v) {
    asm volatile("red.add.release.gpu.u32 [%0], %1;" :: "l"(p), "r"(v) : "memory");
}

// ---------------------------------------------------------------------------
// Kernel 1: x_proj[t][gate][h] = b_gate[h] + sum_i x[63,t,i] * Wgate_x[i,h]
// grid (16, 32): blockIdx.x = col chunk (4 per gate), blockIdx.y = 32-t chunk
// ---------------------------------------------------------------------------
__global__ __launch_bounds__(256) void xproj_kernel(
    const float* __restrict__ x,
    const float* __restrict__ Wfx, const float* __restrict__ bf,
    const float* __restrict__ Wix, const float* __restrict__ bi,
    const float* __restrict__ Wgx, const float* __restrict__ bg,
    const float* __restrict__ Wox, const float* __restrict__ bo)
{
    __shared__ float xs[32][IDIM];   // 32 KB

    const float* x63 = x + (size_t)63 * T_STEPS * IDIM;
    const int tid    = threadIdx.x;
    const int cc     = blockIdx.x;             // 0..15
    const int tchunk = blockIdx.y;             // 0..31
    const int gate   = cc >> 2;                // f=0, i=1, g=2, o=3
    const int col    = ((cc & 3) << 8) + tid;  // h-column within gate

    const float* W;
    const float* b;
    if      (gate == 0) { W = Wfx; b = bf; }
    else if (gate == 1) { W = Wix; b = bi; }
    else if (gate == 2) { W = Wgx; b = bg; }
    else                { W = Wox; b = bo; }

    #pragma unroll 4
    for (int k = 0; k < 32; k++)
        xs[k][tid] = x63[(size_t)(tchunk * 32 + k) * IDIM + tid];
    __syncthreads();

    float acc[32];
    #pragma unroll
    for (int t = 0; t < 32; t++) acc[t] = 0.f;

    for (int i = 0; i < IDIM; i++) {
        float wv = __ldg(&W[(size_t)i * HDIM + col]);
        #pragma unroll
        for (int t = 0; t < 32; t++)
            acc[t] = fmaf(xs[t][i], wv, acc[t]);
    }

    const float bias = __ldg(&b[col]);
    #pragma unroll
    for (int t = 0; t < 32; t++)
        g_xproj[(size_t)(tchunk * 32 + t) * 4096 + gate * HDIM + col] = acc[t] + bias;
}

// ---------------------------------------------------------------------------
// Kernel 2: persistent recurrence over 1024 steps.
// CTA c owns h-cols [8c, 8c+8). Warp w owns rows [64w, 64w+64); lane j maps
// to (gate = j>>3, hh = j&7). Register-resident Wh slice per thread.
//
// h state rotates over NBUF=4 global buffers: step t reads buf[t%4], writes
// buf[(t+1)%4]. Grid sync per step: release-atomic arrival on a counting
// barrier + acquire-poll, both with architectural acq/rel semantics.
// 128 CTAs (<=148 SMs, launch_bounds occupancy 1) => all resident, no
// deadlock in the spin barrier.
// ---------------------------------------------------------------------------
__global__ __launch_bounds__(REC_THREADS, 1) void rec_kernel(
    const float* __restrict__ Wfh, const float* __restrict__ Wih,
    const float* __restrict__ Wgh, const float* __restrict__ Woh,
    const float* __restrict__ Wph, const float* __restrict__ bp,
    float* __restrict__ out)
{
    __shared__ __align__(16) float hs[HDIM];
    __shared__ float partial[16][33];
    __shared__ float gsm[32];

    const int tid  = threadIdx.x;
    const int w    = tid >> 5;
    const int lane = tid & 31;
    const int c    = blockIdx.x;

    const int gate = lane >> 3;
    const int hh   = lane & 7;
    const int hcol = c * 8 + hh;

    const float* Wp = (gate == 0) ? Wfh : (gate == 1) ? Wih : (gate == 2) ? Wgh : Woh;

    // Register-resident weight column slice: Wreg[k] = Wgate[64w + k][hcol]
    float Wreg[64];
    {
        const float* base = Wp + (size_t)(w * 64) * HDIM + hcol;
        #pragma unroll
        for (int k = 0; k < 64; k++)
            Wreg[k] = base[(size_t)k * HDIM];
    }

    float Creg = 0.f;  // cell state, lanes 0..7 of warp 0 (one per h-col)

    for (int t = 0; t < T_STEPS; t++) {
        const float* hin  = g_hbuf[t & (NBUF - 1)];
        float*       hout = g_hbuf[(t + 1) & (NBUF - 1)];

        // Stage h into smem (L2-coherent loads; L1 bypass)
        hs[tid]       = __ldcg(&hin[tid]);
        hs[tid + 512] = __ldcg(&hin[tid + 512]);

        // Warp 0 prefetches its xproj operand; the load retires under the GEMV
        float xp = 0.f;
        if (w == 0)
            xp = __ldg(&g_xproj[(size_t)t * 4096 + gate * HDIM + hcol]);
        __syncthreads();

        // GEMV partial: 64 rows x 1 column per thread
        const float4* h4 = (const float4*)&hs[w * 64];
        float a0 = 0.f, a1 = 0.f, a2 = 0.f, a3 = 0.f;
        #pragma unroll
        for (int k = 0; k < 16; k++) {
            float4 hv = h4[k];
            a0 = fmaf(Wreg[4 * k + 0], hv.x, a0);
            a1 = fmaf(Wreg[4 * k + 1], hv.y, a1);
            a2 = fmaf(Wreg[4 * k + 2], hv.z, a2);
            a3 = fmaf(Wreg[4 * k + 3], hv.w, a3);
        }
        partial[w][lane] = (a0 + a1) + (a2 + a3);
        __syncthreads();

        if (w == 0) {
            // Full dot product for (gate, hcol)
            float s = xp;
            #pragma unroll
            for (int ww = 0; ww < 16; ww++) s += partial[ww][lane];

            // All four gates use sigmoid (per reference)
            const float sg = 1.f / (1.f + expf(-s));
            gsm[lane] = sg;
            __syncwarp();

            if (lane < 8) {
                const float fv = gsm[lane];
                const float iv = gsm[lane + 8];
                const float gv = gsm[lane + 16];
                const float ov = gsm[lane + 24];
                Creg = fmaf(Creg, fv, gv * iv);        // C = C*f + g*i
                __stcg(&hout[hcol], ov * tanhf(Creg)); // h = o*tanh(C), L2-direct
            }
            __threadfence();   // every lane fences its own store (gpu scope)
            __syncwarp();      // order lanes 1..7's fenced stores before lane 0
            if (lane == 0) red_release_gpu(&g_bar, 1u);  // release arrival
        }

        // Acquire poll by thread 0, then block-wide propagation
        if (tid == 0) {
            const unsigned target = (unsigned)(t + 1) * REC_CTAS;
            while (ld_acquire_gpu(&g_bar) < target) { }
        }
        __syncthreads();
    }

    // Head: y[p] = bp[p] + sum_h h_final[h] * Wph[h][p]   (CTA 0 only)
    // Final h lives in g_hbuf[T_STEPS % NBUF] == g_hbuf[0].
    if (c == 0 && tid < 32 * PDIM) {
        const float* hf = g_hbuf[T_STEPS & (NBUF - 1)];
        const int p = tid >> 5;
        float acc = 0.f;
        for (int k = lane; k < HDIM; k += 32)
            acc = fmaf(__ldcg(&hf[k]), __ldg(&Wph[(size_t)k * PDIM + p]), acc);
        #pragma unroll
        for (int off = 16; off; off >>= 1)
            acc += __shfl_down_sync(0xffffffffu, acc, off);
        if (lane == 0) out[p] = acc + __ldg(&bp[p]);
    }
}

// ---------------------------------------------------------------------------
extern "C" void kernel_launch(void* const* d_in, const int* in_sizes, int n_in,
                              void* d_out, int out_size)
{
    const float* x   = (const float*)d_in[0];
    const float* Wfx = (const float*)d_in[1];
    const float* Wfh = (const float*)d_in[2];
    const float* bf  = (const float*)d_in[3];
    const float* Wix = (const float*)d_in[4];
    const float* Wih = (const float*)d_in[5];
    const float* bi  = (const float*)d_in[6];
    const float* Wgx = (const float*)d_in[7];
    const float* Wgh = (const float*)d_in[8];
    const float* bg  = (const float*)d_in[9];
    const float* Wox = (const float*)d_in[10];
    const float* Woh = (const float*)d_in[11];
    const float* bo  = (const float*)d_in[12];
    const float* Wph = (const float*)d_in[13];
    const float* bp  = (const float*)d_in[14];
    float* out = (float*)d_out;

    void* d_h   = nullptr;
    void* d_bar = nullptr;
    cudaGetSymbolAddress(&d_h, g_hbuf);
    cudaGetSymbolAddress(&d_bar, g_bar);
    cudaMemsetAsync(d_h, 0, NBUF * HDIM * sizeof(float));
    cudaMemsetAsync(d_bar, 0, sizeof(unsigned));

    xproj_kernel<<<dim3(16, 32), 256>>>(x, Wfx, bf, Wix, bi, Wgx, bg, Wox, bo);
    rec_kernel<<<REC_CTAS, REC_THREADS>>>(Wfh, Wih, Wgh, Woh, Wph, bp, out);
}

// round 4
// speedup vs baseline: 1.7461x; 1.7461x over previous
#include <cuda_runtime.h>
#include <cuda_bf16.h>
#include <math.h>

// Problem shape (fixed): B=64, T=1024, I=256, H=1024, P=10
// Output depends only on batch sample 63 (h[-1]); LSTM recurrence is
// independent per batch row, so we compute only sample 63's trajectory.
//
// Synchronization design: NO global barrier. Each h value is published as an
// 8-byte {tag=step, value} word with st.relaxed.gpu.b64; consumers poll the
// data itself with ld.relaxed.gpu.b64 until the tag matches the step they
// need. 8B relaxed atomics make tag+value indivisible, so no fences are
// required anywhere. Buffers rotate over NBUF=4 slots; tag = step number
// disambiguates reuse exactly.

#define T_STEPS 1024
#define IDIM    256
#define HDIM    1024
#define PDIM    10

#define REC_CTAS    128   // CTA c owns h-cols [8c, 8c+8) -> 32 gate columns
#define REC_THREADS 512   // 16 warps; warp w consumes h rows [64w, 64w+64)
#define NBUF        4

typedef unsigned long long u64;

// Scratch (static device globals; no allocation allowed)
__device__ float g_xproj[T_STEPS * 4 * HDIM];  // [t][gate][h], bias folded
__device__ u64   g_hbuf[NBUF][HDIM];           // {tag<<32 | f32 bits(h)}

// ---------------------------------------------------------------------------
// PTX helpers
// ---------------------------------------------------------------------------
__device__ __forceinline__ u64 ld_relaxed_gpu(const u64* p) {
    u64 v;
    asm volatile("ld.relaxed.gpu.b64 %0, [%1];" : "=l"(v) : "l"(p) : "memory");
    return v;
}
__device__ __forceinline__ void st_relaxed_gpu(u64* p, u64 v) {
    asm volatile("st.relaxed.gpu.b64 [%0], %1;" :: "l"(p), "l"(v) : "memory");
}
__device__ __forceinline__ u64 ffma2(u64 a, u64 b, u64 c) {
    u64 d;
    asm("fma.rn.f32x2 %0, %1, %2, %3;" : "=l"(d) : "l"(a), "l"(b), "l"(c));
    return d;
}
__device__ __forceinline__ u64 pack2(float lo, float hi) {
    u64 d;
    asm("mov.b64 %0, {%1, %2};" : "=l"(d) : "f"(lo), "f"(hi));
    return d;
}
__device__ __forceinline__ float2 unpack2(u64 v) {
    float lo, hi;
    asm("mov.b64 {%0, %1}, %2;" : "=f"(lo), "=f"(hi) : "l"(v));
    return make_float2(lo, hi);
}
__device__ __forceinline__ void bar_sync_named(int id, int cnt) {
    asm volatile("bar.sync %0, %1;" :: "r"(id), "r"(cnt) : "memory");
}
__device__ __forceinline__ void bar_arrive_named(int id, int cnt) {
    asm volatile("bar.arrive %0, %1;" :: "r"(id), "r"(cnt) : "memory");
}

// ---------------------------------------------------------------------------
// Kernel 1: x_proj[t][gate][h] = b_gate[h] + sum_i x[63,t,i] * Wgate_x[i,h]
// grid (16, 32): blockIdx.x = col chunk (4 per gate), blockIdx.y = 32-t chunk
// ---------------------------------------------------------------------------
__global__ __launch_bounds__(256) void xproj_kernel(
    const float* __restrict__ x,
    const float* __restrict__ Wfx, const float* __restrict__ bf,
    const float* __restrict__ Wix, const float* __restrict__ bi,
    const float* __restrict__ Wgx, const float* __restrict__ bg,
    const float* __restrict__ Wox, const float* __restrict__ bo)
{
    __shared__ float xs[32][IDIM];   // 32 KB

    const float* x63 = x + (size_t)63 * T_STEPS * IDIM;
    const int tid    = threadIdx.x;
    const int cc     = blockIdx.x;             // 0..15
    const int tchunk = blockIdx.y;             // 0..31
    const int gate   = cc >> 2;                // f=0, i=1, g=2, o=3
    const int col    = ((cc & 3) << 8) + tid;  // h-column within gate

    const float* W;
    const float* b;
    if      (gate == 0) { W = Wfx; b = bf; }
    else if (gate == 1) { W = Wix; b = bi; }
    else if (gate == 2) { W = Wgx; b = bg; }
    else                { W = Wox; b = bo; }

    #pragma unroll 4
    for (int k = 0; k < 32; k++)
        xs[k][tid] = x63[(size_t)(tchunk * 32 + k) * IDIM + tid];
    __syncthreads();

    float acc[32];
    #pragma unroll
    for (int t = 0; t < 32; t++) acc[t] = 0.f;

    for (int i = 0; i < IDIM; i++) {
        float wv = __ldg(&W[(size_t)i * HDIM + col]);
        #pragma unroll
        for (int t = 0; t < 32; t++)
            acc[t] = fmaf(xs[t][i], wv, acc[t]);
    }

    const float bias = __ldg(&b[col]);
    #pragma unroll
    for (int t = 0; t < 32; t++)
        g_xproj[(size_t)(tchunk * 32 + t) * 4096 + gate * HDIM + col] = acc[t] + bias;
}

// ---------------------------------------------------------------------------
// Kernel 2: persistent recurrence, 1024 steps, tag-polling synchronization.
//
// Warp w (16 per CTA) owns rows [64w, 64w+64): lane l polls h[64w+2l(+1)]
// with tag==t, stages to its private smem row, does 32 packed f32x2 FMAs
// against register-resident weight pairs, writes one partial.
// Warp 0 gathers partials after a named bar.sync (producers bar.arrive,
// non-blocking), applies sigmoid gates + cell update, and publishes the 8
// new h values with tag t+1. Parity-alternated barrier IDs + parity-buffered
// partials make the <=1-step warp run-ahead race-free.
// ---------------------------------------------------------------------------
__global__ __launch_bounds__(REC_THREADS, 1) void rec_kernel(
    const float* __restrict__ Wfh, const float* __restrict__ Wih,
    const float* __restrict__ Wgh, const float* __restrict__ Woh,
    const float* __restrict__ Wph, const float* __restrict__ bp,
    float* __restrict__ out)
{
    __shared__ __align__(16) float hs[16][64];   // per-warp staged h slice
    __shared__ float partial[2][16][33];         // [parity][warp][gate-col]
    __shared__ float gsm[32];

    const int tid  = threadIdx.x;
    const int w    = tid >> 5;
    const int lane = tid & 31;
    const int c    = blockIdx.x;

    const int gate = lane >> 3;
    const int hh   = lane & 7;
    const int hcol = c * 8 + hh;

    const float* Wp = (gate == 0) ? Wfh : (gate == 1) ? Wih : (gate == 2) ? Wgh : Woh;

    // Register-resident weight pairs: W2[j] = {W[64w+2j][hcol], W[64w+2j+1][hcol]}
    u64 W2[32];
    {
        const float* base = Wp + (size_t)(w * 64) * HDIM + hcol;
        #pragma unroll
        for (int j = 0; j < 32; j++)
            W2[j] = pack2(base[(size_t)(2 * j) * HDIM],
                          base[(size_t)(2 * j + 1) * HDIM]);
    }

    float Creg = 0.f;  // cell state, lanes 0..7 of warp 0 (one per h-col)
    const int e = w * 64 + 2 * lane;  // this lane's two h indices

    for (int t = 0; t < T_STEPS; t++) {
        // warp 0 prefetches its xproj operand (independent of h)
        float xp = 0.f;
        if (w == 0)
            xp = __ldg(&g_xproj[(size_t)t * 4096 + gate * HDIM + hcol]);

        // Poll this lane's two h entries until tagged with step t
        const u64* hin = g_hbuf[t & (NBUF - 1)];
        const unsigned tg = (unsigned)t;
        u64 v0 = ld_relaxed_gpu(&hin[e]);
        while ((unsigned)(v0 >> 32) != tg) v0 = ld_relaxed_gpu(&hin[e]);
        u64 v1 = ld_relaxed_gpu(&hin[e + 1]);
        while ((unsigned)(v1 >> 32) != tg) v1 = ld_relaxed_gpu(&hin[e + 1]);
        hs[w][2 * lane]     = __uint_as_float((unsigned)v0);
        hs[w][2 * lane + 1] = __uint_as_float((unsigned)v1);
        __syncwarp();

        // GEMV partial: 64 rows x 1 gate-column, packed f32x2 (32 FFMA2)
        const ulonglong2* hp = reinterpret_cast<const ulonglong2*>(hs[w]);
        u64 acc0 = 0, acc1 = 0, acc2 = 0, acc3 = 0;  // bits {0.f, 0.f}
        #pragma unroll
        for (int k = 0; k < 8; k++) {
            ulonglong2 ha = hp[2 * k];
            ulonglong2 hb = hp[2 * k + 1];
            acc0 = ffma2(W2[4 * k + 0], ha.x, acc0);
            acc1 = ffma2(W2[4 * k + 1], ha.y, acc1);
            acc2 = ffma2(W2[4 * k + 2], hb.x, acc2);
            acc3 = ffma2(W2[4 * k + 3], hb.y, acc3);
        }
        float2 f0 = unpack2(acc0), f1 = unpack2(acc1);
        float2 f2 = unpack2(acc2), f3 = unpack2(acc3);
        partial[t & 1][w][lane] =
            ((f0.x + f0.y) + (f1.x + f1.y)) + ((f2.x + f2.y) + (f3.x + f3.y));

        const int barid = 1 + (t & 1);
        if (w == 0) {
            bar_sync_named(barid, REC_THREADS);   // wait for 15 arrivals + self

            float s = xp;
            #pragma unroll
            for (int ww = 0; ww < 16; ww++) s += partial[t & 1][ww][lane];

            // All four gates are sigmoid (per reference)
            const float sg = __fdividef(1.f, 1.f + __expf(-s));
            gsm[lane] = sg;
            __syncwarp();

            if (lane < 8) {
                const float fv = gsm[lane];
                const float iv = gsm[lane + 8];
                const float gv = gsm[lane + 16];
                const float ov = gsm[lane + 24];
                Creg = fmaf(Creg, fv, gv * iv);      // C = C*f + g*i
                const float hn = ov * tanhf(Creg);   // h = o*tanh(C)
                const u64 pk = ((u64)(unsigned)(t + 1) << 32)
                             | (u64)__float_as_uint(hn);
                st_relaxed_gpu(&g_hbuf[(t + 1) & (NBUF - 1)][hcol], pk);
            }
        } else {
            __threadfence_block();                // order partial[] before arrive
            bar_arrive_named(barid, REC_THREADS); // non-blocking producer arrive
        }
    }

    // Head: y[p] = bp[p] + sum_h h_final[h] * Wph[h][p]   (CTA 0 only)
    // Final h has tag T_STEPS in slot T_STEPS % NBUF == 0; poll tags.
    if (c == 0 && tid < 32 * PDIM) {
        const u64* hf = g_hbuf[T_STEPS & (NBUF - 1)];
        const int p = tid >> 5;
        float acc = 0.f;
        for (int k = lane; k < HDIM; k += 32) {
            u64 v = ld_relaxed_gpu(&hf[k]);
            while ((unsigned)(v >> 32) != (unsigned)T_STEPS)
                v = ld_relaxed_gpu(&hf[k]);
            acc = fmaf(__uint_as_float((unsigned)v),
                       __ldg(&Wph[(size_t)k * PDIM + p]), acc);
        }
        #pragma unroll
        for (int off = 16; off; off >>= 1)
            acc += __shfl_down_sync(0xffffffffu, acc, off);
        if (lane == 0) out[p] = acc + __ldg(&bp[p]);
    }
}

// ---------------------------------------------------------------------------
extern "C" void kernel_launch(void* const* d_in, const int* in_sizes, int n_in,
                              void* d_out, int out_size)
{
    const float* x   = (const float*)d_in[0];
    const float* Wfx = (const float*)d_in[1];
    const float* Wfh = (const float*)d_in[2];
    const float* bf  = (const float*)d_in[3];
    const float* Wix = (const float*)d_in[4];
    const float* Wih = (const float*)d_in[5];
    const float* bi  = (const float*)d_in[6];
    const float* Wgx = (const float*)d_in[7];
    const float* Wgh = (const float*)d_in[8];
    const float* bg  = (const float*)d_in[9];
    const float* Wox = (const float*)d_in[10];
    const float* Woh = (const float*)d_in[11];
    const float* bo  = (const float*)d_in[12];
    const float* Wph = (const float*)d_in[13];
    const float* bp  = (const float*)d_in[14];
    float* out = (float*)d_out;

    // Zero tags (tag 0 == "h^0 ready, value 0") -- this IS the initial state.
    void* d_h = nullptr;
    cudaGetSymbolAddress(&d_h, g_hbuf);
    cudaMemsetAsync(d_h, 0, NBUF * HDIM * sizeof(u64));

    xproj_kernel<<<dim3(16, 32), 256>>>(x, Wfx, bf, Wix, bi, Wgx, bg, Wox, bo);
    rec_kernel<<<REC_CTAS, REC_THREADS>>>(Wfh, Wih, Wgh, Woh, Wph, bp, out);
}

// round 6
// speedup vs baseline: 1.8019x; 1.0320x over previous
#include <cuda_runtime.h>
#include <cuda_bf16.h>
#include <math.h>

// Problem shape (fixed): B=64, T=1024, I=256, H=1024, P=10
// Output depends only on batch sample 63 (h[-1]); LSTM recurrence is
// independent per batch row, so we compute only sample 63's trajectory.
//
// Sync design: NO global barrier. Each h value is an 8-byte {tag=step, value}
// word published with st.relaxed.gpu.b64 and consumed by polling
// ld.relaxed.gpu.b64 until tag matches. 8B relaxed atomicity removes all
// fence requirements. Buffers rotate over NBUF=4 slots.

#define T_STEPS 1024
#define IDIM    256
#define HDIM    1024
#define PDIM    10

#define REC_CTAS    128   // CTA c owns h-cols [8c, 8c+8) -> 32 gate columns
#define REC_THREADS 544   // warp 0 = reducer; warps 1..16 = GEMV producers
#define NBUF        4

typedef unsigned long long u64;

// Scratch (static device globals; no allocation allowed)
__device__ float g_xproj[T_STEPS * 4 * HDIM];  // [t][gate][h], bias folded
__device__ u64   g_hbuf[NBUF][HDIM];           // {tag<<32 | f32 bits(h)}

// ---------------------------------------------------------------------------
// PTX helpers
// ---------------------------------------------------------------------------
__device__ __forceinline__ u64 ld_relaxed_gpu(const u64* p) {
    u64 v;
    asm volatile("ld.relaxed.gpu.b64 %0, [%1];" : "=l"(v) : "l"(p) : "memory");
    return v;
}
__device__ __forceinline__ void st_relaxed_gpu(u64* p, u64 v) {
    asm volatile("st.relaxed.gpu.b64 [%0], %1;" :: "l"(p), "l"(v) : "memory");
}
__device__ __forceinline__ u64 ffma2(u64 a, u64 b, u64 c) {
    u64 d;
    asm("fma.rn.f32x2 %0, %1, %2, %3;" : "=l"(d) : "l"(a), "l"(b), "l"(c));
    return d;
}
__device__ __forceinline__ u64 pack2(float lo, float hi) {
    u64 d;
    asm("mov.b64 %0, {%1, %2};" : "=l"(d) : "f"(lo), "f"(hi));
    return d;
}
__device__ __forceinline__ float2 unpack2(u64 v) {
    float lo, hi;
    asm("mov.b64 {%0, %1}, %2;" : "=f"(lo), "=f"(hi) : "l"(v));
    return make_float2(lo, hi);
}
__device__ __forceinline__ void bar_sync_named(int id, int cnt) {
    asm volatile("bar.sync %0, %1;" :: "r"(id), "r"(cnt) : "memory");
}
__device__ __forceinline__ void bar_arrive_named(int id, int cnt) {
    asm volatile("bar.arrive %0, %1;" :: "r"(id), "r"(cnt) : "memory");
}
// tanh via MUFU: 1 - 2/(exp(2x)+1). Saturates correctly for |x| large.
__device__ __forceinline__ float fast_tanh(float x) {
    return 1.f - __fdividef(2.f, __expf(2.f * x) + 1.f);
}

// ---------------------------------------------------------------------------
// Kernel 1: x_proj[t][gate][h] = b_gate[h] + sum_i x[63,t,i] * Wgate_x[i,h]
// ---------------------------------------------------------------------------
__global__ __launch_bounds__(256) void xproj_kernel(
    const float* __restrict__ x,
    const float* __restrict__ Wfx, const float* __restrict__ bf,
    const float* __restrict__ Wix, const float* __restrict__ bi,
    const float* __restrict__ Wgx, const float* __restrict__ bg,
    const float* __restrict__ Wox, const float* __restrict__ bo)
{
    __shared__ float xs[32][IDIM];   // 32 KB

    const float* x63 = x + (size_t)63 * T_STEPS * IDIM;
    const int tid    = threadIdx.x;
    const int cc     = blockIdx.x;             // 0..15
    const int tchunk = blockIdx.y;             // 0..31
    const int gate   = cc >> 2;                // f=0, i=1, g=2, o=3
    const int col    = ((cc & 3) << 8) + tid;  // h-column within gate

    const float* W;
    const float* b;
    if      (gate == 0) { W = Wfx; b = bf; }
    else if (gate == 1) { W = Wix; b = bi; }
    else if (gate == 2) { W = Wgx; b = bg; }
    else                { W = Wox; b = bo; }

    #pragma unroll 4
    for (int k = 0; k < 32; k++)
        xs[k][tid] = x63[(size_t)(tchunk * 32 + k) * IDIM + tid];
    __syncthreads();

    float acc[32];
    #pragma unroll
    for (int t = 0; t < 32; t++) acc[t] = 0.f;

    for (int i = 0; i < IDIM; i++) {
        float wv = __ldg(&W[(size_t)i * HDIM + col]);
        #pragma unroll
        for (int t = 0; t < 32; t++)
            acc[t] = fmaf(xs[t][i], wv, acc[t]);
    }

    const float bias = __ldg(&b[col]);
    #pragma unroll
    for (int t = 0; t < 32; t++)
        g_xproj[(size_t)(tchunk * 32 + t) * 4096 + gate * HDIM + col] = acc[t] + bias;
}

// ---------------------------------------------------------------------------
// Kernel 2: persistent recurrence, 1024 steps, tag-polling synchronization.
// Warps 1..16: warp w consumes h rows [64(w-1), 64w): pipelined tag-poll,
//   smem stage, 32 packed f32x2 FMAs against register-resident weight pairs,
//   one partial, non-blocking bar.arrive.
// Warp 0: prefetches xproj, bar.sync, treed 16->1 reduce, sigmoid gates,
//   cell update + fast tanh, publishes 8 tagged h values.
// partial[] is single-buffered: producers cannot write step-(t+1) partials
// until warp 0 published h(t+1), which happens after its step-t reduce.
// ---------------------------------------------------------------------------
__global__ __launch_bounds__(REC_THREADS, 1) void rec_kernel(
    const float* __restrict__ Wfh, const float* __restrict__ Wih,
    const float* __restrict__ Wgh, const float* __restrict__ Woh,
    const float* __restrict__ Wph, const float* __restrict__ bp,
    float* __restrict__ out)
{
    __shared__ __align__(16) float hs[16][64];   // per-producer-warp h slice
    __shared__ float partial[16][33];            // [producer][gate-col]

    const int tid  = threadIdx.x;
    const int w    = tid >> 5;
    const int lane = tid & 31;
    const int c    = blockIdx.x;

    const int gate = lane >> 3;
    const int hh   = lane & 7;
    const int hcol = c * 8 + hh;

    if (w == 0) {
        // ---------------- Reducer warp ----------------
        float Creg = 0.f;  // lanes 0..7 hold C for h-cols [8c, 8c+8)
        const float* xpp = &g_xproj[(size_t)gate * HDIM + hcol];

        for (int t = 0; t < T_STEPS; t++) {
            const float xp = __ldg(xpp + (size_t)t * 4096);  // hidden by bar wait
            bar_sync_named(1 + (t & 1), REC_THREADS);

            // Treed 16 -> 1 reduction of producer partials
            float p0 = partial[ 0][lane], p1 = partial[ 1][lane];
            float p2 = partial[ 2][lane], p3 = partial[ 3][lane];
            float p4 = partial[ 4][lane], p5 = partial[ 5][lane];
            float p6 = partial[ 6][lane], p7 = partial[ 7][lane];
            float p8 = partial[ 8][lane], p9 = partial[ 9][lane];
            float pa = partial[10][lane], pb = partial[11][lane];
            float pc = partial[12][lane], pd = partial[13][lane];
            float pe = partial[14][lane], pf = partial[15][lane];
            float s = (((p0 + p1) + (p2 + p3)) + ((p4 + p5) + (p6 + p7)))
                    + (((p8 + p9) + (pa + pb)) + ((pc + pd) + (pe + pf)))
                    + xp;

            // All four gates are sigmoid (per reference)
            const float sg = __fdividef(1.f, 1.f + __expf(-s));
            const float iv = __shfl_sync(0xffffffffu, sg,  8 + hh);
            const float gv = __shfl_sync(0xffffffffu, sg, 16 + hh);
            const float ov = __shfl_sync(0xffffffffu, sg, 24 + hh);
            if (lane < 8) {
                Creg = fmaf(Creg, sg, gv * iv);          // C = C*f + g*i
                const float hn = ov * fast_tanh(Creg);   // h = o*tanh(C)
                const u64 pk = ((u64)(unsigned)(t + 1) << 32)
                             | (u64)__float_as_uint(hn);
                st_relaxed_gpu(&g_hbuf[(t + 1) & (NBUF - 1)][hcol], pk);
            }
        }
    } else {
        // ---------------- Producer warps 1..16 ----------------
        const int pw = w - 1;                 // producer index 0..15
        const float* Wp = (gate == 0) ? Wfh : (gate == 1) ? Wih
                        : (gate == 2) ? Wgh : Woh;

        // Register-resident weight pairs for rows [64*pw, 64*pw+64)
        u64 W2[32];
        {
            const float* base = Wp + (size_t)(pw * 64) * HDIM + hcol;
            #pragma unroll
            for (int j = 0; j < 32; j++)
                W2[j] = pack2(base[(size_t)(2 * j) * HDIM],
                              base[(size_t)(2 * j + 1) * HDIM]);
        }

        const int e = pw * 64 + 2 * lane;     // this lane's two h indices

        for (int t = 0; t < T_STEPS; t++) {
            // Pipelined poll: next loads issued before testing current ones
            const u64* hin = g_hbuf[t & (NBUF - 1)];
            const unsigned tg = (unsigned)t;
            u64 v0 = ld_relaxed_gpu(&hin[e]);
            u64 v1 = ld_relaxed_gpu(&hin[e + 1]);
            while ((unsigned)(v0 >> 32) != tg || (unsigned)(v1 >> 32) != tg) {
                u64 n0 = ld_relaxed_gpu(&hin[e]);
                u64 n1 = ld_relaxed_gpu(&hin[e + 1]);
                v0 = n0; v1 = n1;
            }
            hs[pw][2 * lane]     = __uint_as_float((unsigned)v0);
            hs[pw][2 * lane + 1] = __uint_as_float((unsigned)v1);
            __syncwarp();

            // GEMV partial: 64 rows x 1 gate-column, packed f32x2
            const ulonglong2* hp = reinterpret_cast<const ulonglong2*>(hs[pw]);
            u64 acc0 = 0, acc1 = 0, acc2 = 0, acc3 = 0;  // {0.f, 0.f} bits
            #pragma unroll
            for (int k = 0; k < 8; k++) {
                ulonglong2 ha = hp[2 * k];
                ulonglong2 hb = hp[2 * k + 1];
                acc0 = ffma2(W2[4 * k + 0], ha.x, acc0);
                acc1 = ffma2(W2[4 * k + 1], ha.y, acc1);
                acc2 = ffma2(W2[4 * k + 2], hb.x, acc2);
                acc3 = ffma2(W2[4 * k + 3], hb.y, acc3);
            }
            float2 f0 = unpack2(acc0), f1 = unpack2(acc1);
            float2 f2 = unpack2(acc2), f3 = unpack2(acc3);
            partial[pw][lane] =
                ((f0.x + f0.y) + (f1.x + f1.y)) + ((f2.x + f2.y) + (f3.x + f3.y));

            __threadfence_block();                       // order partial write
            bar_arrive_named(1 + (t & 1), REC_THREADS);  // non-blocking
        }
    }

    // Head: y[p] = bp[p] + sum_h h_final[h] * Wph[h][p]   (CTA 0 only)
    if (c == 0 && tid < 32 * PDIM) {
        const u64* hf = g_hbuf[T_STEPS & (NBUF - 1)];
        const int p = tid >> 5;
        float acc = 0.f;
        for (int k = lane; k < HDIM; k += 32) {
            u64 v = ld_relaxed_gpu(&hf[k]);
            while ((unsigned)(v >> 32) != (unsigned)T_STEPS)
                v = ld_relaxed_gpu(&hf[k]);
            acc = fmaf(__uint_as_float((unsigned)v),
                       __ldg(&Wph[(size_t)k * PDIM + p]), acc);
        }
        #pragma unroll
        for (int off = 16; off; off >>= 1)
            acc += __shfl_down_sync(0xffffffffu, acc, off);
        if (lane == 0) out[p] = acc + __ldg(&bp[p]);
    }
}

// ---------------------------------------------------------------------------
extern "C" void kernel_launch(void* const* d_in, const int* in_sizes, int n_in,
                              void* d_out, int out_size)
{
    const float* x   = (const float*)d_in[0];
    const float* Wfx = (const float*)d_in[1];
    const float* Wfh = (const float*)d_in[2];
    const float* bf  = (const float*)d_in[3];
    const float* Wix = (const float*)d_in[4];
    const float* Wih = (const float*)d_in[5];
    const float* bi  = (const float*)d_in[6];
    const float* Wgx = (const float*)d_in[7];
    const float* Wgh = (const float*)d_in[8];
    const float* bg  = (const float*)d_in[9];
    const float* Wox = (const float*)d_in[10];
    const float* Woh = (const float*)d_in[11];
    const float* bo  = (const float*)d_in[12];
    const float* Wph = (const float*)d_in[13];
    const float* bp  = (const float*)d_in[14];
    float* out = (float*)d_out;

    // Tag 0 == "h^0 ready, value 0" -- zeroing IS the initial state.
    void* d_h = nullptr;
    cudaGetSymbolAddress(&d_h, g_hbuf);
    cudaMemsetAsync(d_h, 0, NBUF * HDIM * sizeof(u64));

    xproj_kernel<<<dim3(16, 32), 256>>>(x, Wfx, bf, Wix, bi, Wgx, bg, Wox, bo);
    rec_kernel<<<REC_CTAS, REC_THREADS>>>(Wfh, Wih, Wgh, Woh, Wph, bp, out);
}